// round 1
// baseline (speedup 1.0000x reference)
#include <cuda_runtime.h>

// Problem constants
namespace {
constexpr int kB   = 64;
constexpr int kS   = 128;
constexpr int kL   = 512;
constexpr int kVEC = 512;
constexpr int kHID = 1024;
constexpr int kRows = kB * kS;          // 8192
constexpr int kOut  = kVEC + kHID;      // 1536
}

// Scratch (no allocations allowed -> device globals)
__device__ float g_Q[(size_t)kRows * kHID];   // 33.5 MB
__device__ float g_P[(size_t)kRows * kL];     // 16.7 MB (scores, then attn in place)
__device__ int   g_is64;

// ---------------------------------------------------------------------------
// Probe: detect whether `skills` is int64 or int32.
// If int64 (little-endian), every odd 32-bit word is the high word of a value
// < 20001 -> zero. If int32, odd words are random values in [0, 20001): the
// probability all 64 sampled are zero is ~(1/20001)^64 ~= 0.
// ---------------------------------------------------------------------------
__global__ void probe_kernel(const int* __restrict__ s32) {
    int any = 0;
    for (int i = 1; i < 128; i += 2) any |= s32[i];
    g_is64 = (any == 0) ? 1 : 0;
}

__device__ __forceinline__ int skill_at(const int* __restrict__ s32, int row) {
    return g_is64 ? s32[2 * row] : s32[row];
}

// ---------------------------------------------------------------------------
// Gather sk rows into out[:, 0:512]
// ---------------------------------------------------------------------------
__global__ void gather_kernel(const int* __restrict__ s32,
                              const float* __restrict__ emb,
                              float* __restrict__ out) {
    const int row = blockIdx.x;
    const int idx = skill_at(s32, row);
    const float4* src = (const float4*)(emb + (size_t)idx * kVEC);
    float4* dst = (float4*)(out + (size_t)row * kOut);
    dst[threadIdx.x] = src[threadIdx.x];   // 128 threads * float4 = 512 floats
}

// ---------------------------------------------------------------------------
// GEMM1: Q[8192,1024] = gather(emb, skills)[8192,512] @ W[512,1024]
// Tile 128x64, BK=16, 256 threads, 8x4 micro-tile.
// ---------------------------------------------------------------------------
__global__ __launch_bounds__(256) void gemm1_kernel(const int* __restrict__ s32,
                                                    const float* __restrict__ emb,
                                                    const float* __restrict__ W) {
    __shared__ __align__(16) float As[16][132];   // [k][m], +4 pad
    __shared__ __align__(16) float Bs[16][68];    // [k][n], +4 pad
    __shared__ int sIdx[128];

    const int tid = threadIdx.x;
    const int m0 = blockIdx.y * 128;
    const int n0 = blockIdx.x * 64;

    if (tid < 128) sIdx[tid] = skill_at(s32, m0 + tid);
    __syncthreads();

    const int tm  = (tid >> 4) * 8;
    const int tn  = (tid & 15) * 4;
    const int ar  = tid >> 2;          // 0..63
    const int akq = (tid & 3) * 4;     // 0,4,8,12
    const int bk  = tid >> 4;          // 0..15
    const int bn  = (tid & 15) * 4;

    float acc[8][4] = {};

    for (int k0 = 0; k0 < kVEC; k0 += 16) {
#pragma unroll
        for (int it = 0; it < 2; ++it) {
            const int r = ar + it * 64;
            float4 v = *(const float4*)(emb + (size_t)sIdx[r] * kVEC + k0 + akq);
            As[akq + 0][r] = v.x; As[akq + 1][r] = v.y;
            As[akq + 2][r] = v.z; As[akq + 3][r] = v.w;
        }
        *(float4*)&Bs[bk][bn] =
            *(const float4*)(W + (size_t)(k0 + bk) * kHID + n0 + bn);
        __syncthreads();
#pragma unroll
        for (int kk = 0; kk < 16; ++kk) {
            float4 a0 = *(const float4*)&As[kk][tm];
            float4 a1 = *(const float4*)&As[kk][tm + 4];
            float4 b0 = *(const float4*)&Bs[kk][tn];
            const float a[8] = {a0.x, a0.y, a0.z, a0.w, a1.x, a1.y, a1.z, a1.w};
            const float b[4] = {b0.x, b0.y, b0.z, b0.w};
#pragma unroll
            for (int i = 0; i < 8; ++i)
#pragma unroll
                for (int j = 0; j < 4; ++j)
                    acc[i][j] = fmaf(a[i], b[j], acc[i][j]);
        }
        __syncthreads();
    }
#pragma unroll
    for (int i = 0; i < 8; ++i)
        *(float4*)(g_Q + (size_t)(m0 + tm + i) * kHID + n0 + tn) =
            make_float4(acc[i][0], acc[i][1], acc[i][2], acc[i][3]);
}

// ---------------------------------------------------------------------------
// GEMM2 (NT, per batch): scores[b][s][l] = sum_h Q[b,s,h] * desc[b,l,h]
// Tile 64x64, BK=16, 256 threads, 4x4 micro-tile -> 1024 CTAs total.
// ---------------------------------------------------------------------------
__global__ __launch_bounds__(256) void gemm2_kernel(const float* __restrict__ desc) {
    __shared__ __align__(16) float As[16][68];
    __shared__ __align__(16) float Bs[16][68];

    const int tid = threadIdx.x;
    const int b  = blockIdx.z;
    const int m0 = blockIdx.y * 64;
    const int n0 = blockIdx.x * 64;

    const int tm = (tid >> 4) * 4;
    const int tn = (tid & 15) * 4;
    const int r  = tid >> 2;           // 0..63
    const int kq = (tid & 3) * 4;

    const float* Qb = g_Q + (size_t)b * kS * kHID;
    const float* Db = desc + (size_t)b * kL * kHID;

    float acc[4][4] = {};

    for (int k0 = 0; k0 < kHID; k0 += 16) {
        {
            float4 v = *(const float4*)(Qb + (size_t)(m0 + r) * kHID + k0 + kq);
            As[kq + 0][r] = v.x; As[kq + 1][r] = v.y;
            As[kq + 2][r] = v.z; As[kq + 3][r] = v.w;
        }
        {
            float4 v = *(const float4*)(Db + (size_t)(n0 + r) * kHID + k0 + kq);
            Bs[kq + 0][r] = v.x; Bs[kq + 1][r] = v.y;
            Bs[kq + 2][r] = v.z; Bs[kq + 3][r] = v.w;
        }
        __syncthreads();
#pragma unroll
        for (int kk = 0; kk < 16; ++kk) {
            float4 a0 = *(const float4*)&As[kk][tm];
            float4 b0 = *(const float4*)&Bs[kk][tn];
            const float a[4] = {a0.x, a0.y, a0.z, a0.w};
            const float bb[4] = {b0.x, b0.y, b0.z, b0.w};
#pragma unroll
            for (int i = 0; i < 4; ++i)
#pragma unroll
                for (int j = 0; j < 4; ++j)
                    acc[i][j] = fmaf(a[i], bb[j], acc[i][j]);
        }
        __syncthreads();
    }
#pragma unroll
    for (int i = 0; i < 4; ++i)
        *(float4*)(g_P + (size_t)(b * kS + m0 + tm + i) * kL + n0 + tn) =
            make_float4(acc[i][0], acc[i][1], acc[i][2], acc[i][3]);
}

// ---------------------------------------------------------------------------
// Softmax over rows of g_P (8192 rows x 512). One warp per row.
// ---------------------------------------------------------------------------
__global__ void softmax_kernel() {
    const int lane = threadIdx.x & 31;
    const int warp = threadIdx.x >> 5;
    const int row = blockIdx.x * 8 + warp;
    float4* p = (float4*)(g_P + (size_t)row * kL);

    float4 v[4];
    float mx = -1e30f;
#pragma unroll
    for (int i = 0; i < 4; ++i) {
        v[i] = p[lane + 32 * i];
        mx = fmaxf(mx, fmaxf(fmaxf(v[i].x, v[i].y), fmaxf(v[i].z, v[i].w)));
    }
#pragma unroll
    for (int o = 16; o; o >>= 1) mx = fmaxf(mx, __shfl_xor_sync(0xffffffffu, mx, o));

    float sum = 0.f;
#pragma unroll
    for (int i = 0; i < 4; ++i) {
        v[i].x = __expf(v[i].x - mx); sum += v[i].x;
        v[i].y = __expf(v[i].y - mx); sum += v[i].y;
        v[i].z = __expf(v[i].z - mx); sum += v[i].z;
        v[i].w = __expf(v[i].w - mx); sum += v[i].w;
    }
#pragma unroll
    for (int o = 16; o; o >>= 1) sum += __shfl_xor_sync(0xffffffffu, sum, o);

    const float inv = 1.0f / sum;
#pragma unroll
    for (int i = 0; i < 4; ++i) {
        v[i].x *= inv; v[i].y *= inv; v[i].z *= inv; v[i].w *= inv;
        p[lane + 32 * i] = v[i];
    }
}

// ---------------------------------------------------------------------------
// GEMM3 (NN, per batch): ctx[b][s][h] = sum_l attn[b,s,l] * desc[b,l,h]
// Tile 128x64, BK=16, 256 threads, 8x4 micro-tile. Writes out[:, 512:1536].
// ---------------------------------------------------------------------------
__global__ __launch_bounds__(256) void gemm3_kernel(const float* __restrict__ desc,
                                                    float* __restrict__ out) {
    __shared__ __align__(16) float As[16][132];
    __shared__ __align__(16) float Bs[16][68];

    const int tid = threadIdx.x;
    const int b  = blockIdx.z;
    const int n0 = blockIdx.x * 64;

    const int tm  = (tid >> 4) * 8;
    const int tn  = (tid & 15) * 4;
    const int ar  = tid >> 2;
    const int akq = (tid & 3) * 4;
    const int bk  = tid >> 4;
    const int bn  = (tid & 15) * 4;

    const float* Pb = g_P + (size_t)b * kS * kL;
    const float* Db = desc + (size_t)b * kL * kHID;

    float acc[8][4] = {};

    for (int k0 = 0; k0 < kL; k0 += 16) {
#pragma unroll
        for (int it = 0; it < 2; ++it) {
            const int r = ar + it * 64;
            float4 v = *(const float4*)(Pb + (size_t)r * kL + k0 + akq);
            As[akq + 0][r] = v.x; As[akq + 1][r] = v.y;
            As[akq + 2][r] = v.z; As[akq + 3][r] = v.w;
        }
        *(float4*)&Bs[bk][bn] =
            *(const float4*)(Db + (size_t)(k0 + bk) * kHID + n0 + bn);
        __syncthreads();
#pragma unroll
        for (int kk = 0; kk < 16; ++kk) {
            float4 a0 = *(const float4*)&As[kk][tm];
            float4 a1 = *(const float4*)&As[kk][tm + 4];
            float4 b0 = *(const float4*)&Bs[kk][tn];
            const float a[8] = {a0.x, a0.y, a0.z, a0.w, a1.x, a1.y, a1.z, a1.w};
            const float bb[4] = {b0.x, b0.y, b0.z, b0.w};
#pragma unroll
            for (int i = 0; i < 8; ++i)
#pragma unroll
                for (int j = 0; j < 4; ++j)
                    acc[i][j] = fmaf(a[i], bb[j], acc[i][j]);
        }
        __syncthreads();
    }
#pragma unroll
    for (int i = 0; i < 8; ++i)
        *(float4*)(out + (size_t)(b * kS + tm + i) * kOut + kVEC + n0 + tn) =
            make_float4(acc[i][0], acc[i][1], acc[i][2], acc[i][3]);
}

// ---------------------------------------------------------------------------
// Launch
// ---------------------------------------------------------------------------
extern "C" void kernel_launch(void* const* d_in, const int* in_sizes, int n_in,
                              void* d_out, int out_size) {
    (void)in_sizes; (void)n_in; (void)out_size;
    const int*   s32  = (const int*)d_in[0];    // skills (int64 or int32, probed)
    const float* desc = (const float*)d_in[1];  // [B, L, HID]
    const float* emb  = (const float*)d_in[2];  // [VOCAB, VEC]
    const float* W    = (const float*)d_in[3];  // [VEC, HID]
    float* out = (float*)d_out;                 // [B, S*(VEC+HID)]

    probe_kernel<<<1, 1>>>(s32);
    gather_kernel<<<kRows, 128>>>(s32, emb, out);

    { dim3 g(kHID / 64, kRows / 128); gemm1_kernel<<<g, 256>>>(s32, emb, W); }
    { dim3 g(kL / 64, kS / 64, kB);   gemm2_kernel<<<g, 256>>>(desc); }
    softmax_kernel<<<kRows / 8, 256>>>();
    { dim3 g(kHID / 64, 1, kB);       gemm3_kernel<<<g, 256>>>(desc, out); }
}